// round 4
// baseline (speedup 1.0000x reference)
#include <cuda_runtime.h>

#define NB 32
#define NS 128
#define NSKILL 256
#define DK 128
#define HPAD 132            // padded row length for h in smem (bank-conflict avoidance)

// ---- shared memory layout (floats) ----
#define OFF_H    0                      // 256*132 = 33792
#define OFF_WFT  33792                  // 128*128 = 16384
#define OFF_KVT  (OFF_WFT + 16384)      // 256
#define OFF_KVN  (OFF_KVT + 256)       // 256
#define OFF_X4   (OFF_KVN + 256)       // 512 : [learning | itv | lv | h_tilde]
#define OFF_LG   (OFF_X4 + 512)        // 128
#define OFF_LGV  (OFF_LG + 128)        // 128
#define OFF_GTV  (OFF_LGV + 128)       // 128
#define OFF_CT   (OFF_GTV + 128)       // 128
#define OFF_EXN  (OFF_CT + 128)        // 128
#define OFF_PART (OFF_EXN + 128)       // 512
#define SMEM_FLOATS (OFF_PART + 512)   // 52352 floats = 209408 bytes

__device__ float g_le[NB * NS * DK];   // precomputed learning embedding
__device__ float g_ansW[DK];           // rowsum of W1 answer block

__device__ __forceinline__ float sigm(float x) {
    return __fdividef(1.0f, 1.0f + __expf(-x));
}

// ---------------- precompute: ansW[d] = sum_k W1[d, 256+k] ----------------
__global__ void answ_kernel(const float* __restrict__ W1) {
    int d = threadIdx.x;
    float a = 0.f;
    #pragma unroll 8
    for (int k = 0; k < 128; k++) a += W1[d * 384 + 256 + k];
    g_ansW[d] = a;
}

// ---------------- precompute: le[b,t,:] for all (b,t) ----------------
__global__ void le_kernel(const int* __restrict__ eid, const int* __restrict__ atid,
                          const int* __restrict__ av,
                          const float* __restrict__ ex_table,
                          const float* __restrict__ at_table,
                          const float* __restrict__ W1, const float* __restrict__ b1) {
    __shared__ float exs[128], ats[128];
    int bt = blockIdx.x;          // 0 .. B*S-1
    int d = threadIdx.x;
    exs[d] = ex_table[eid[bt] * 128 + d];
    ats[d] = at_table[atid[bt] * 128 + d];
    __syncthreads();
    const float* row = W1 + d * 384;
    float acc = b1[d] + (float)av[bt] * g_ansW[d];
    #pragma unroll 8
    for (int k = 0; k < 128; k++) {
        acc = fmaf(row[k], exs[k], acc);
        acc = fmaf(row[128 + k], ats[k], acc);
    }
    g_le[bt * 128 + d] = acc;
}

// ---------------- main persistent recurrence: 1 CTA per batch ----------------
__global__ __launch_bounds__(512, 1) void lpkt_main(
    const int* __restrict__ eid, const int* __restrict__ itid,
    const float* __restrict__ qm,
    const float* __restrict__ ex_table, const float* __restrict__ it_table,
    const float* __restrict__ Wl, const float* __restrict__ bl,
    const float* __restrict__ Wg, const float* __restrict__ bg,
    const float* __restrict__ Wf, const float* __restrict__ bf,
    const float* __restrict__ Wp, const float* __restrict__ bp,
    const float* __restrict__ h0,
    float* __restrict__ out)
{
    extern __shared__ float sm[];
    float* h    = sm + OFF_H;
    float* wfT  = sm + OFF_WFT;
    float* kvt  = sm + OFF_KVT;
    float* kvn  = sm + OFF_KVN;
    float* x4   = sm + OFF_X4;
    float* LG   = sm + OFF_LG;
    float* lgv  = sm + OFF_LGV;
    float* gtv  = sm + OFF_GTV;
    float* ct   = sm + OFF_CT;
    float* exn  = sm + OFF_EXN;
    float* part = sm + OFF_PART;

    const int b = blockIdx.x;
    const int tid = threadIdx.x;

    // --- load Wf_h^T into smem: wfT[k*128+d] = Wf[d*384+k]
    for (int i = tid; i < 128 * 128; i += 512) {
        int d = i & 127, k = i >> 7;
        wfT[i] = Wf[d * 384 + k];
    }
    // --- load h0 into smem (padded rows)
    for (int i = tid; i < NSKILL * DK; i += 512) {
        int s = i >> 7, k = i & 127;
        h[s * HPAD + k] = h0[i];
    }
    __syncthreads();

    // --- initial h_tilde = kv[:,0] . h0 ---
    {
        int e0 = eid[b * NS + 0];
        if (tid < 256) kvn[tid] = qm[e0 * NSKILL + tid];
    }
    __syncthreads();
    {
        int d = tid & 127, c = tid >> 7;
        float a = 0.f;
        const float* kp = kvn + c * 64;
        const float* hp = h + (c * 64) * HPAD + d;
        #pragma unroll 8
        for (int s = 0; s < 64; s++) a = fmaf(kp[s], hp[s * HPAD], a);
        part[c * 128 + d] = a;
    }
    __syncthreads();
    if (tid < 128)
        x4[384 + tid] = part[tid] + part[128 + tid] + part[256 + tid] + part[384 + tid];
    __syncthreads();

    for (int t = 0; t < NS - 1; t++) {
        // ---------- Phase A: gathers + build x4 ----------
        const int e_t = eid[b * NS + t];
        const int e_n = eid[b * NS + t + 1];
        const int it_n = itid[b * NS + t + 1];
        if (tid < 128) {
            float oldlv = (t == 0) ? 0.f : x4[256 + tid];   // learning_pre = prev lv
            x4[tid]        = oldlv;
            x4[128 + tid]  = it_table[it_n * 128 + tid];    // itv
            x4[256 + tid]  = g_le[(b * NS + t) * 128 + tid];// lv
            exn[tid]       = ex_table[e_n * 128 + tid];
        } else {
            int s = tid - 128;
            if (s < 256) {
                kvt[s] = qm[e_t * NSKILL + s];
                kvn[s] = qm[e_n * NSKILL + s];
            }
        }
        __syncthreads();

        // ---------- Phase B: lg / gate (x4 @ Wl^T, x4 @ Wg^T), split-K by 2 ----------
        {
            int which = tid >> 8;              // 0 -> Wl, 1 -> Wg
            int r = tid & 255;
            int d = r >> 1, half = r & 1;
            const float* Wrow = (which ? Wg : Wl) + d * 512 + half * 256;
            const float* xv = x4 + half * 256;
            float a = 0.f;
            #pragma unroll 8
            for (int k = 0; k < 256; k++) a = fmaf(Wrow[k], xv[k], a);
            part[tid] = a;
        }
        __syncthreads();
        if (tid < 256) {
            int which = tid >> 7, d = tid & 127;
            float v = part[which * 256 + d * 2] + part[which * 256 + d * 2 + 1];
            if (which == 0) lgv[d] = tanhf(v + bl[d]);
            else            gtv[d] = sigm(v + bg[d]);
        }
        __syncthreads();
        if (tid < 128) LG[tid] = gtv[tid] * (lgv[tid] + 1.0f) * 0.5f;
        __syncthreads();

        // ---------- cterm[d] = LG . Wf[d,128:256] + itv . Wf[d,256:384] ----------
        if (tid < 256) {
            int d = tid >> 1, half = tid & 1;
            const float* row = Wf + d * 384 + 128 + half * 128;
            const float* vec = half ? (x4 + 128) : LG;
            float a = 0.f;
            #pragma unroll 8
            for (int k = 0; k < 128; k++) a = fmaf(row[k], vec[k], a);
            part[tid] = a;
        }
        __syncthreads();
        if (tid < 128) ct[tid] = part[tid * 2] + part[tid * 2 + 1] + bf[tid];
        __syncthreads();

        // ---------- Phase C: f = sigmoid(h @ Wf_h^T + ct); h = kv_t*LG + f*h ----------
        {
            const int d0 = (tid & 15) * 4;      // covers d0..d0+3 and d0+64..d0+67
            const int s0 = (tid >> 4) * 8;      // 8 consecutive skills
            float acc[8][8];
            #pragma unroll
            for (int i = 0; i < 8; i++)
                #pragma unroll
                for (int j = 0; j < 8; j++) acc[i][j] = 0.f;

            #pragma unroll 1
            for (int k = 0; k < 128; k += 4) {
                #pragma unroll
                for (int kk = 0; kk < 4; kk++) {
                    float4 wa = *(const float4*)(wfT + (k + kk) * 128 + d0);
                    float4 wb = *(const float4*)(wfT + (k + kk) * 128 + d0 + 64);
                    #pragma unroll
                    for (int i = 0; i < 8; i++) {
                        float hx = h[(s0 + i) * HPAD + k + kk];
                        acc[i][0] = fmaf(hx, wa.x, acc[i][0]);
                        acc[i][1] = fmaf(hx, wa.y, acc[i][1]);
                        acc[i][2] = fmaf(hx, wa.z, acc[i][2]);
                        acc[i][3] = fmaf(hx, wa.w, acc[i][3]);
                        acc[i][4] = fmaf(hx, wb.x, acc[i][4]);
                        acc[i][5] = fmaf(hx, wb.y, acc[i][5]);
                        acc[i][6] = fmaf(hx, wb.z, acc[i][6]);
                        acc[i][7] = fmaf(hx, wb.w, acc[i][7]);
                    }
                }
            }
            __syncthreads();   // all dot-product reads of h finished

            #pragma unroll
            for (int i = 0; i < 8; i++) {
                int s = s0 + i;
                float kvts = kvt[s];
                #pragma unroll
                for (int j = 0; j < 8; j++) {
                    int d = (j < 4) ? (d0 + j) : (d0 + 60 + j);
                    float fv = sigm(acc[i][j] + ct[d]);
                    float hn = fmaf(fv, h[s * HPAD + d], kvts * LG[d]);
                    h[s * HPAD + d] = hn;     // exclusive (s,d) tile per thread
                }
            }
        }
        __syncthreads();

        // ---------- Phase D: h_tilde = kv_next . h ; pred ----------
        {
            int d = tid & 127, c = tid >> 7;
            float a = 0.f;
            const float* kp = kvn + c * 64;
            const float* hp = h + (c * 64) * HPAD + d;
            #pragma unroll 8
            for (int s = 0; s < 64; s++) a = fmaf(kp[s], hp[s * HPAD], a);
            part[c * 128 + d] = a;
        }
        __syncthreads();
        if (tid < 128)
            x4[384 + tid] = part[tid] + part[128 + tid] + part[256 + tid] + part[384 + tid];
        __syncthreads();
        if (tid < 128) {
            int d = tid;
            const float* row = Wp + d * 256;
            float a = bp[d];
            #pragma unroll 8
            for (int k = 0; k < 128; k++) {
                a = fmaf(exn[k], row[k], a);
                a = fmaf(x4[384 + k], row[128 + k], a);
            }
            out[(b * (NS - 1) + t) * 128 + d] = sigm(a);
        }
        __syncthreads();
    }
}

extern "C" void kernel_launch(void* const* d_in, const int* in_sizes, int n_in,
                              void* d_out, int out_size) {
    const int*   eid       = (const int*)d_in[0];
    const int*   atid      = (const int*)d_in[1];
    const int*   itid      = (const int*)d_in[2];
    const int*   av        = (const int*)d_in[3];
    const float* qm        = (const float*)d_in[4];
    const float* ex_table  = (const float*)d_in[5];
    const float* at_table  = (const float*)d_in[6];
    const float* it_table  = (const float*)d_in[7];
    const float* W1        = (const float*)d_in[8];
    const float* b1        = (const float*)d_in[9];
    const float* Wl        = (const float*)d_in[10];
    const float* bl        = (const float*)d_in[11];
    const float* Wg        = (const float*)d_in[12];
    const float* bg        = (const float*)d_in[13];
    const float* Wf        = (const float*)d_in[14];
    const float* bf        = (const float*)d_in[15];
    const float* Wp        = (const float*)d_in[16];
    const float* bp        = (const float*)d_in[17];
    const float* h0        = (const float*)d_in[18];
    float* out = (float*)d_out;

    size_t smem_bytes = (size_t)SMEM_FLOATS * sizeof(float);
    cudaFuncSetAttribute(lpkt_main, cudaFuncAttributeMaxDynamicSharedMemorySize,
                         (int)smem_bytes);

    answ_kernel<<<1, 128>>>(W1);
    le_kernel<<<NB * NS, 128>>>(eid, atid, av, ex_table, at_table, W1, b1);
    lpkt_main<<<NB, 512, smem_bytes>>>(eid, itid, qm, ex_table, it_table,
                                       Wl, bl, Wg, bg, Wf, bf, Wp, bp, h0, out);
}

// round 5
// speedup vs baseline: 1.0001x; 1.0001x over previous
#include <cuda_runtime.h>

#define NB 32
#define NS 128
#define NSKILL 256
#define DK 128
#define HPAD 132            // padded row length for h in smem (bank-conflict avoidance)

// ---- shared memory layout (floats) ----
#define OFF_H    0                      // 256*132 = 33792
#define OFF_WFT  33792                  // 128*128 = 16384
#define OFF_KVT  (OFF_WFT + 16384)      // 256
#define OFF_KVN  (OFF_KVT + 256)       // 256
#define OFF_X4   (OFF_KVN + 256)       // 512 : [learning | itv | lv | h_tilde]
#define OFF_LG   (OFF_X4 + 512)        // 128
#define OFF_LGV  (OFF_LG + 128)        // 128
#define OFF_GTV  (OFF_LGV + 128)       // 128
#define OFF_CT   (OFF_GTV + 128)       // 128
#define OFF_EXN  (OFF_CT + 128)        // 128
#define OFF_PART (OFF_EXN + 128)       // 512
#define SMEM_FLOATS (OFF_PART + 512)   // 52352 floats = 209408 bytes

__device__ float g_le[NB * NS * DK];   // precomputed learning embedding
__device__ float g_ansW[DK];           // rowsum of W1 answer block

__device__ __forceinline__ float sigm(float x) {
    return __fdividef(1.0f, 1.0f + __expf(-x));
}

// ---------------- precompute: ansW[d] = sum_k W1[d, 256+k] ----------------
__global__ void answ_kernel(const float* __restrict__ W1) {
    int d = threadIdx.x;
    float a = 0.f;
    #pragma unroll 8
    for (int k = 0; k < 128; k++) a += W1[d * 384 + 256 + k];
    g_ansW[d] = a;
}

// ---------------- precompute: le[b,t,:] for all (b,t) ----------------
__global__ void le_kernel(const int* __restrict__ eid, const int* __restrict__ atid,
                          const int* __restrict__ av,
                          const float* __restrict__ ex_table,
                          const float* __restrict__ at_table,
                          const float* __restrict__ W1, const float* __restrict__ b1) {
    __shared__ float exs[128], ats[128];
    int bt = blockIdx.x;          // 0 .. B*S-1
    int d = threadIdx.x;
    exs[d] = ex_table[eid[bt] * 128 + d];
    ats[d] = at_table[atid[bt] * 128 + d];
    __syncthreads();
    const float* row = W1 + d * 384;
    float acc = b1[d] + (float)av[bt] * g_ansW[d];
    #pragma unroll 8
    for (int k = 0; k < 128; k++) {
        acc = fmaf(row[k], exs[k], acc);
        acc = fmaf(row[128 + k], ats[k], acc);
    }
    g_le[bt * 128 + d] = acc;
}

// ---------------- main persistent recurrence: 1 CTA per batch ----------------
__global__ __launch_bounds__(512, 1) void lpkt_main(
    const int* __restrict__ eid, const int* __restrict__ itid,
    const float* __restrict__ qm,
    const float* __restrict__ ex_table, const float* __restrict__ it_table,
    const float* __restrict__ Wl, const float* __restrict__ bl,
    const float* __restrict__ Wg, const float* __restrict__ bg,
    const float* __restrict__ Wf, const float* __restrict__ bf,
    const float* __restrict__ Wp, const float* __restrict__ bp,
    const float* __restrict__ h0,
    float* __restrict__ out)
{
    extern __shared__ float sm[];
    float* h    = sm + OFF_H;
    float* wfT  = sm + OFF_WFT;
    float* kvt  = sm + OFF_KVT;
    float* kvn  = sm + OFF_KVN;
    float* x4   = sm + OFF_X4;
    float* LG   = sm + OFF_LG;
    float* lgv  = sm + OFF_LGV;
    float* gtv  = sm + OFF_GTV;
    float* ct   = sm + OFF_CT;
    float* exn  = sm + OFF_EXN;
    float* part = sm + OFF_PART;

    const int b = blockIdx.x;
    const int tid = threadIdx.x;

    // --- load Wf_h^T into smem: wfT[k*128+d] = Wf[d*384+k]
    for (int i = tid; i < 128 * 128; i += 512) {
        int d = i & 127, k = i >> 7;
        wfT[i] = Wf[d * 384 + k];
    }
    // --- load h0 into smem (padded rows)
    for (int i = tid; i < NSKILL * DK; i += 512) {
        int s = i >> 7, k = i & 127;
        h[s * HPAD + k] = h0[i];
    }
    __syncthreads();

    // --- initial h_tilde = kv[:,0] . h0 ---
    {
        int e0 = eid[b * NS + 0];
        if (tid < 256) kvn[tid] = qm[e0 * NSKILL + tid];
    }
    __syncthreads();
    {
        int d = tid & 127, c = tid >> 7;
        float a = 0.f;
        const float* kp = kvn + c * 64;
        const float* hp = h + (c * 64) * HPAD + d;
        #pragma unroll 8
        for (int s = 0; s < 64; s++) a = fmaf(kp[s], hp[s * HPAD], a);
        part[c * 128 + d] = a;
    }
    __syncthreads();
    if (tid < 128)
        x4[384 + tid] = part[tid] + part[128 + tid] + part[256 + tid] + part[384 + tid];
    __syncthreads();

    for (int t = 0; t < NS - 1; t++) {
        // ---------- Phase A: gathers + build x4 ----------
        const int e_t = eid[b * NS + t];
        const int e_n = eid[b * NS + t + 1];
        const int it_n = itid[b * NS + t + 1];
        if (tid < 128) {
            float oldlv = (t == 0) ? 0.f : x4[256 + tid];   // learning_pre = prev lv
            x4[tid]        = oldlv;
            x4[128 + tid]  = it_table[it_n * 128 + tid];    // itv
            x4[256 + tid]  = g_le[(b * NS + t) * 128 + tid];// lv
            exn[tid]       = ex_table[e_n * 128 + tid];
        } else {
            int s = tid - 128;
            if (s < 256) {
                kvt[s] = qm[e_t * NSKILL + s];
                kvn[s] = qm[e_n * NSKILL + s];
            }
        }
        __syncthreads();

        // ---------- Phase B: lg / gate (x4 @ Wl^T, x4 @ Wg^T), split-K by 2 ----------
        {
            int which = tid >> 8;              // 0 -> Wl, 1 -> Wg
            int r = tid & 255;
            int d = r >> 1, half = r & 1;
            const float* Wrow = (which ? Wg : Wl) + d * 512 + half * 256;
            const float* xv = x4 + half * 256;
            float a = 0.f;
            #pragma unroll 8
            for (int k = 0; k < 256; k++) a = fmaf(Wrow[k], xv[k], a);
            part[tid] = a;
        }
        __syncthreads();
        if (tid < 256) {
            int which = tid >> 7, d = tid & 127;
            float v = part[which * 256 + d * 2] + part[which * 256 + d * 2 + 1];
            if (which == 0) lgv[d] = tanhf(v + bl[d]);
            else            gtv[d] = sigm(v + bg[d]);
        }
        __syncthreads();
        if (tid < 128) LG[tid] = gtv[tid] * (lgv[tid] + 1.0f) * 0.5f;
        __syncthreads();

        // ---------- cterm[d] = LG . Wf[d,128:256] + itv . Wf[d,256:384] ----------
        if (tid < 256) {
            int d = tid >> 1, half = tid & 1;
            const float* row = Wf + d * 384 + 128 + half * 128;
            const float* vec = half ? (x4 + 128) : LG;
            float a = 0.f;
            #pragma unroll 8
            for (int k = 0; k < 128; k++) a = fmaf(row[k], vec[k], a);
            part[tid] = a;
        }
        __syncthreads();
        if (tid < 128) ct[tid] = part[tid * 2] + part[tid * 2 + 1] + bf[tid];
        __syncthreads();

        // ---------- Phase C: f = sigmoid(h @ Wf_h^T + ct); h = kv_t*LG + f*h ----------
        {
            const int d0 = (tid & 15) * 4;      // covers d0..d0+3 and d0+64..d0+67
            const int s0 = (tid >> 4) * 8;      // 8 consecutive skills
            float acc[8][8];
            #pragma unroll
            for (int i = 0; i < 8; i++)
                #pragma unroll
                for (int j = 0; j < 8; j++) acc[i][j] = 0.f;

            #pragma unroll 1
            for (int k = 0; k < 128; k += 4) {
                #pragma unroll
                for (int kk = 0; kk < 4; kk++) {
                    float4 wa = *(const float4*)(wfT + (k + kk) * 128 + d0);
                    float4 wb = *(const float4*)(wfT + (k + kk) * 128 + d0 + 64);
                    #pragma unroll
                    for (int i = 0; i < 8; i++) {
                        float hx = h[(s0 + i) * HPAD + k + kk];
                        acc[i][0] = fmaf(hx, wa.x, acc[i][0]);
                        acc[i][1] = fmaf(hx, wa.y, acc[i][1]);
                        acc[i][2] = fmaf(hx, wa.z, acc[i][2]);
                        acc[i][3] = fmaf(hx, wa.w, acc[i][3]);
                        acc[i][4] = fmaf(hx, wb.x, acc[i][4]);
                        acc[i][5] = fmaf(hx, wb.y, acc[i][5]);
                        acc[i][6] = fmaf(hx, wb.z, acc[i][6]);
                        acc[i][7] = fmaf(hx, wb.w, acc[i][7]);
                    }
                }
            }
            __syncthreads();   // all dot-product reads of h finished

            #pragma unroll
            for (int i = 0; i < 8; i++) {
                int s = s0 + i;
                float kvts = kvt[s];
                #pragma unroll
                for (int j = 0; j < 8; j++) {
                    int d = (j < 4) ? (d0 + j) : (d0 + 60 + j);
                    float fv = sigm(acc[i][j] + ct[d]);
                    float hn = fmaf(fv, h[s * HPAD + d], kvts * LG[d]);
                    h[s * HPAD + d] = hn;     // exclusive (s,d) tile per thread
                }
            }
        }
        __syncthreads();

        // ---------- Phase D: h_tilde = kv_next . h ; pred ----------
        {
            int d = tid & 127, c = tid >> 7;
            float a = 0.f;
            const float* kp = kvn + c * 64;
            const float* hp = h + (c * 64) * HPAD + d;
            #pragma unroll 8
            for (int s = 0; s < 64; s++) a = fmaf(kp[s], hp[s * HPAD], a);
            part[c * 128 + d] = a;
        }
        __syncthreads();
        if (tid < 128)
            x4[384 + tid] = part[tid] + part[128 + tid] + part[256 + tid] + part[384 + tid];
        __syncthreads();
        if (tid < 128) {
            int d = tid;
            const float* row = Wp + d * 256;
            float a = bp[d];
            #pragma unroll 8
            for (int k = 0; k < 128; k++) {
                a = fmaf(exn[k], row[k], a);
                a = fmaf(x4[384 + k], row[128 + k], a);
            }
            out[(b * (NS - 1) + t) * 128 + d] = sigm(a);
        }
        __syncthreads();
    }
}

extern "C" void kernel_launch(void* const* d_in, const int* in_sizes, int n_in,
                              void* d_out, int out_size) {
    const int*   eid       = (const int*)d_in[0];
    const int*   atid      = (const int*)d_in[1];
    const int*   itid      = (const int*)d_in[2];
    const int*   av        = (const int*)d_in[3];
    const float* qm        = (const float*)d_in[4];
    const float* ex_table  = (const float*)d_in[5];
    const float* at_table  = (const float*)d_in[6];
    const float* it_table  = (const float*)d_in[7];
    const float* W1        = (const float*)d_in[8];
    const float* b1        = (const float*)d_in[9];
    const float* Wl        = (const float*)d_in[10];
    const float* bl        = (const float*)d_in[11];
    const float* Wg        = (const float*)d_in[12];
    const float* bg        = (const float*)d_in[13];
    const float* Wf        = (const float*)d_in[14];
    const float* bf        = (const float*)d_in[15];
    const float* Wp        = (const float*)d_in[16];
    const float* bp        = (const float*)d_in[17];
    const float* h0        = (const float*)d_in[18];
    float* out = (float*)d_out;

    size_t smem_bytes = (size_t)SMEM_FLOATS * sizeof(float);
    cudaFuncSetAttribute(lpkt_main, cudaFuncAttributeMaxDynamicSharedMemorySize,
                         (int)smem_bytes);

    answ_kernel<<<1, 128>>>(W1);
    le_kernel<<<NB * NS, 128>>>(eid, atid, av, ex_table, at_table, W1, b1);
    lpkt_main<<<NB, 512, smem_bytes>>>(eid, itid, qm, ex_table, it_table,
                                       Wl, bl, Wg, bg, Wf, bf, Wp, bp, h0, out);
}

// round 6
// speedup vs baseline: 1.0010x; 1.0010x over previous
#include <cuda_runtime.h>

#define NB 32
#define NS 128
#define NSKILL 256
#define DK 128
#define HPAD 132            // padded row length for h in smem (bank-conflict avoidance)

// ---- shared memory layout (floats) ----
#define OFF_H    0                      // 256*132 = 33792
#define OFF_WFT  33792                  // 128*128 = 16384
#define OFF_KVT  (OFF_WFT + 16384)      // 256
#define OFF_KVN  (OFF_KVT + 256)       // 256
#define OFF_X4   (OFF_KVN + 256)       // 512 : [learning | itv | lv | h_tilde]
#define OFF_LG   (OFF_X4 + 512)        // 128
#define OFF_LGV  (OFF_LG + 128)        // 128
#define OFF_GTV  (OFF_LGV + 128)       // 128
#define OFF_CT   (OFF_GTV + 128)       // 128
#define OFF_EXN  (OFF_CT + 128)        // 128
#define OFF_PART (OFF_EXN + 128)       // 512
#define SMEM_FLOATS (OFF_PART + 512)   // 52352 floats = 209408 bytes

__device__ float g_le[NB * NS * DK];   // precomputed learning embedding
__device__ float g_ansW[DK];           // rowsum of W1 answer block

__device__ __forceinline__ float sigm(float x) {
    return __fdividef(1.0f, 1.0f + __expf(-x));
}

// ---------------- precompute: ansW[d] = sum_k W1[d, 256+k] ----------------
__global__ void answ_kernel(const float* __restrict__ W1) {
    int d = threadIdx.x;
    float a = 0.f;
    #pragma unroll 8
    for (int k = 0; k < 128; k++) a += W1[d * 384 + 256 + k];
    g_ansW[d] = a;
}

// ---------------- precompute: le[b,t,:] for all (b,t) ----------------
__global__ void le_kernel(const int* __restrict__ eid, const int* __restrict__ atid,
                          const int* __restrict__ av,
                          const float* __restrict__ ex_table,
                          const float* __restrict__ at_table,
                          const float* __restrict__ W1, const float* __restrict__ b1) {
    __shared__ float exs[128], ats[128];
    int bt = blockIdx.x;          // 0 .. B*S-1
    int d = threadIdx.x;
    exs[d] = ex_table[eid[bt] * 128 + d];
    ats[d] = at_table[atid[bt] * 128 + d];
    __syncthreads();
    const float* row = W1 + d * 384;
    float acc = b1[d] + (float)av[bt] * g_ansW[d];
    #pragma unroll 8
    for (int k = 0; k < 128; k++) {
        acc = fmaf(row[k], exs[k], acc);
        acc = fmaf(row[128 + k], ats[k], acc);
    }
    g_le[bt * 128 + d] = acc;
}

// ---------------- main persistent recurrence: 1 CTA per batch ----------------
__global__ __launch_bounds__(512, 1) void lpkt_main(
    const int* __restrict__ eid, const int* __restrict__ itid,
    const float* __restrict__ qm,
    const float* __restrict__ ex_table, const float* __restrict__ it_table,
    const float* __restrict__ Wl, const float* __restrict__ bl,
    const float* __restrict__ Wg, const float* __restrict__ bg,
    const float* __restrict__ Wf, const float* __restrict__ bf,
    const float* __restrict__ Wp, const float* __restrict__ bp,
    const float* __restrict__ h0,
    float* __restrict__ out)
{
    extern __shared__ float sm[];
    float* h    = sm + OFF_H;
    float* wfT  = sm + OFF_WFT;
    float* kvt  = sm + OFF_KVT;
    float* kvn  = sm + OFF_KVN;
    float* x4   = sm + OFF_X4;
    float* LG   = sm + OFF_LG;
    float* lgv  = sm + OFF_LGV;
    float* gtv  = sm + OFF_GTV;
    float* ct   = sm + OFF_CT;
    float* exn  = sm + OFF_EXN;
    float* part = sm + OFF_PART;

    const int b = blockIdx.x;
    const int tid = threadIdx.x;

    // --- load Wf_h^T into smem: wfT[k*128+d] = Wf[d*384+k]
    for (int i = tid; i < 128 * 128; i += 512) {
        int d = i & 127, k = i >> 7;
        wfT[i] = Wf[d * 384 + k];
    }
    // --- load h0 into smem (padded rows)
    for (int i = tid; i < NSKILL * DK; i += 512) {
        int s = i >> 7, k = i & 127;
        h[s * HPAD + k] = h0[i];
    }
    __syncthreads();

    // --- initial h_tilde = kv[:,0] . h0 ---
    {
        int e0 = eid[b * NS + 0];
        if (tid < 256) kvn[tid] = qm[e0 * NSKILL + tid];
    }
    __syncthreads();
    {
        int d = tid & 127, c = tid >> 7;
        float a = 0.f;
        const float* kp = kvn + c * 64;
        const float* hp = h + (c * 64) * HPAD + d;
        #pragma unroll 8
        for (int s = 0; s < 64; s++) a = fmaf(kp[s], hp[s * HPAD], a);
        part[c * 128 + d] = a;
    }
    __syncthreads();
    if (tid < 128)
        x4[384 + tid] = part[tid] + part[128 + tid] + part[256 + tid] + part[384 + tid];
    __syncthreads();

    for (int t = 0; t < NS - 1; t++) {
        // ---------- Phase A: gathers + build x4 ----------
        const int e_t = eid[b * NS + t];
        const int e_n = eid[b * NS + t + 1];
        const int it_n = itid[b * NS + t + 1];
        if (tid < 128) {
            float oldlv = (t == 0) ? 0.f : x4[256 + tid];   // learning_pre = prev lv
            x4[tid]        = oldlv;
            x4[128 + tid]  = it_table[it_n * 128 + tid];    // itv
            x4[256 + tid]  = g_le[(b * NS + t) * 128 + tid];// lv
            exn[tid]       = ex_table[e_n * 128 + tid];
        } else {
            int s = tid - 128;
            if (s < 256) {
                kvt[s] = qm[e_t * NSKILL + s];
                kvn[s] = qm[e_n * NSKILL + s];
            }
        }
        __syncthreads();

        // ---------- Phase B: lg / gate (x4 @ Wl^T, x4 @ Wg^T), split-K by 2 ----------
        {
            int which = tid >> 8;              // 0 -> Wl, 1 -> Wg
            int r = tid & 255;
            int d = r >> 1, half = r & 1;
            const float* Wrow = (which ? Wg : Wl) + d * 512 + half * 256;
            const float* xv = x4 + half * 256;
            float a = 0.f;
            #pragma unroll 8
            for (int k = 0; k < 256; k++) a = fmaf(Wrow[k], xv[k], a);
            part[tid] = a;
        }
        __syncthreads();
        if (tid < 256) {
            int which = tid >> 7, d = tid & 127;
            float v = part[which * 256 + d * 2] + part[which * 256 + d * 2 + 1];
            if (which == 0) lgv[d] = tanhf(v + bl[d]);
            else            gtv[d] = sigm(v + bg[d]);
        }
        __syncthreads();
        if (tid < 128) LG[tid] = gtv[tid] * (lgv[tid] + 1.0f) * 0.5f;
        __syncthreads();

        // ---------- cterm[d] = LG . Wf[d,128:256] + itv . Wf[d,256:384] ----------
        if (tid < 256) {
            int d = tid >> 1, half = tid & 1;
            const float* row = Wf + d * 384 + 128 + half * 128;
            const float* vec = half ? (x4 + 128) : LG;
            float a = 0.f;
            #pragma unroll 8
            for (int k = 0; k < 128; k++) a = fmaf(row[k], vec[k], a);
            part[tid] = a;
        }
        __syncthreads();
        if (tid < 128) ct[tid] = part[tid * 2] + part[tid * 2 + 1] + bf[tid];
        __syncthreads();

        // ---------- Phase C: f = sigmoid(h @ Wf_h^T + ct); h = kv_t*LG + f*h ----------
        {
            const int d0 = (tid & 15) * 4;      // covers d0..d0+3 and d0+64..d0+67
            const int s0 = (tid >> 4) * 8;      // 8 consecutive skills
            float acc[8][8];
            #pragma unroll
            for (int i = 0; i < 8; i++)
                #pragma unroll
                for (int j = 0; j < 8; j++) acc[i][j] = 0.f;

            #pragma unroll 1
            for (int k = 0; k < 128; k += 4) {
                #pragma unroll
                for (int kk = 0; kk < 4; kk++) {
                    float4 wa = *(const float4*)(wfT + (k + kk) * 128 + d0);
                    float4 wb = *(const float4*)(wfT + (k + kk) * 128 + d0 + 64);
                    #pragma unroll
                    for (int i = 0; i < 8; i++) {
                        float hx = h[(s0 + i) * HPAD + k + kk];
                        acc[i][0] = fmaf(hx, wa.x, acc[i][0]);
                        acc[i][1] = fmaf(hx, wa.y, acc[i][1]);
                        acc[i][2] = fmaf(hx, wa.z, acc[i][2]);
                        acc[i][3] = fmaf(hx, wa.w, acc[i][3]);
                        acc[i][4] = fmaf(hx, wb.x, acc[i][4]);
                        acc[i][5] = fmaf(hx, wb.y, acc[i][5]);
                        acc[i][6] = fmaf(hx, wb.z, acc[i][6]);
                        acc[i][7] = fmaf(hx, wb.w, acc[i][7]);
                    }
                }
            }
            __syncthreads();   // all dot-product reads of h finished

            #pragma unroll
            for (int i = 0; i < 8; i++) {
                int s = s0 + i;
                float kvts = kvt[s];
                #pragma unroll
                for (int j = 0; j < 8; j++) {
                    int d = (j < 4) ? (d0 + j) : (d0 + 60 + j);
                    float fv = sigm(acc[i][j] + ct[d]);
                    float hn = fmaf(fv, h[s * HPAD + d], kvts * LG[d]);
                    h[s * HPAD + d] = hn;     // exclusive (s,d) tile per thread
                }
            }
        }
        __syncthreads();

        // ---------- Phase D: h_tilde = kv_next . h ; pred ----------
        {
            int d = tid & 127, c = tid >> 7;
            float a = 0.f;
            const float* kp = kvn + c * 64;
            const float* hp = h + (c * 64) * HPAD + d;
            #pragma unroll 8
            for (int s = 0; s < 64; s++) a = fmaf(kp[s], hp[s * HPAD], a);
            part[c * 128 + d] = a;
        }
        __syncthreads();
        if (tid < 128)
            x4[384 + tid] = part[tid] + part[128 + tid] + part[256 + tid] + part[384 + tid];
        __syncthreads();
        if (tid < 128) {
            int d = tid;
            const float* row = Wp + d * 256;
            float a = bp[d];
            #pragma unroll 8
            for (int k = 0; k < 128; k++) {
                a = fmaf(exn[k], row[k], a);
                a = fmaf(x4[384 + k], row[128 + k], a);
            }
            out[(b * (NS - 1) + t) * 128 + d] = sigm(a);
        }
        __syncthreads();
    }
}

extern "C" void kernel_launch(void* const* d_in, const int* in_sizes, int n_in,
                              void* d_out, int out_size) {
    const int*   eid       = (const int*)d_in[0];
    const int*   atid      = (const int*)d_in[1];
    const int*   itid      = (const int*)d_in[2];
    const int*   av        = (const int*)d_in[3];
    const float* qm        = (const float*)d_in[4];
    const float* ex_table  = (const float*)d_in[5];
    const float* at_table  = (const float*)d_in[6];
    const float* it_table  = (const float*)d_in[7];
    const float* W1        = (const float*)d_in[8];
    const float* b1        = (const float*)d_in[9];
    const float* Wl        = (const float*)d_in[10];
    const float* bl        = (const float*)d_in[11];
    const float* Wg        = (const float*)d_in[12];
    const float* bg        = (const float*)d_in[13];
    const float* Wf        = (const float*)d_in[14];
    const float* bf        = (const float*)d_in[15];
    const float* Wp        = (const float*)d_in[16];
    const float* bp        = (const float*)d_in[17];
    const float* h0        = (const float*)d_in[18];
    float* out = (float*)d_out;

    size_t smem_bytes = (size_t)SMEM_FLOATS * sizeof(float);
    cudaFuncSetAttribute(lpkt_main, cudaFuncAttributeMaxDynamicSharedMemorySize,
                         (int)smem_bytes);

    answ_kernel<<<1, 128>>>(W1);
    le_kernel<<<NB * NS, 128>>>(eid, atid, av, ex_table, at_table, W1, b1);
    lpkt_main<<<NB, 512, smem_bytes>>>(eid, itid, qm, ex_table, it_table,
                                       Wl, bl, Wg, bg, Wf, bf, Wp, bp, h0, out);
}

// round 7
// speedup vs baseline: 1.0023x; 1.0012x over previous
#include <cuda_runtime.h>

#define NB 32
#define NS 128
#define NSKILL 256
#define DK 128
#define HPAD 132            // padded row length for h in smem (bank-conflict avoidance)

// ---- shared memory layout (floats) ----
#define OFF_H    0                      // 256*132 = 33792
#define OFF_WFT  33792                  // 128*128 = 16384
#define OFF_KVT  (OFF_WFT + 16384)      // 256
#define OFF_KVN  (OFF_KVT + 256)       // 256
#define OFF_X4   (OFF_KVN + 256)       // 512 : [learning | itv | lv | h_tilde]
#define OFF_LG   (OFF_X4 + 512)        // 128
#define OFF_LGV  (OFF_LG + 128)        // 128
#define OFF_GTV  (OFF_LGV + 128)       // 128
#define OFF_CT   (OFF_GTV + 128)       // 128
#define OFF_EXN  (OFF_CT + 128)        // 128
#define OFF_PART (OFF_EXN + 128)       // 512
#define SMEM_FLOATS (OFF_PART + 512)   // 52352 floats = 209408 bytes

__device__ float g_le[NB * NS * DK];   // precomputed learning embedding
__device__ float g_ansW[DK];           // rowsum of W1 answer block

__device__ __forceinline__ float sigm(float x) {
    return __fdividef(1.0f, 1.0f + __expf(-x));
}

// ---------------- precompute: ansW[d] = sum_k W1[d, 256+k] ----------------
__global__ void answ_kernel(const float* __restrict__ W1) {
    int d = threadIdx.x;
    float a = 0.f;
    #pragma unroll 8
    for (int k = 0; k < 128; k++) a += W1[d * 384 + 256 + k];
    g_ansW[d] = a;
}

// ---------------- precompute: le[b,t,:] for all (b,t) ----------------
__global__ void le_kernel(const int* __restrict__ eid, const int* __restrict__ atid,
                          const int* __restrict__ av,
                          const float* __restrict__ ex_table,
                          const float* __restrict__ at_table,
                          const float* __restrict__ W1, const float* __restrict__ b1) {
    __shared__ float exs[128], ats[128];
    int bt = blockIdx.x;          // 0 .. B*S-1
    int d = threadIdx.x;
    exs[d] = ex_table[eid[bt] * 128 + d];
    ats[d] = at_table[atid[bt] * 128 + d];
    __syncthreads();
    const float* row = W1 + d * 384;
    float acc = b1[d] + (float)av[bt] * g_ansW[d];
    #pragma unroll 8
    for (int k = 0; k < 128; k++) {
        acc = fmaf(row[k], exs[k], acc);
        acc = fmaf(row[128 + k], ats[k], acc);
    }
    g_le[bt * 128 + d] = acc;
}

// ---------------- main persistent recurrence: 1 CTA per batch ----------------
__global__ __launch_bounds__(512, 1) void lpkt_main(
    const int* __restrict__ eid, const int* __restrict__ itid,
    const float* __restrict__ qm,
    const float* __restrict__ ex_table, const float* __restrict__ it_table,
    const float* __restrict__ Wl, const float* __restrict__ bl,
    const float* __restrict__ Wg, const float* __restrict__ bg,
    const float* __restrict__ Wf, const float* __restrict__ bf,
    const float* __restrict__ Wp, const float* __restrict__ bp,
    const float* __restrict__ h0,
    float* __restrict__ out)
{
    extern __shared__ float sm[];
    float* h    = sm + OFF_H;
    float* wfT  = sm + OFF_WFT;
    float* kvt  = sm + OFF_KVT;
    float* kvn  = sm + OFF_KVN;
    float* x4   = sm + OFF_X4;
    float* LG   = sm + OFF_LG;
    float* lgv  = sm + OFF_LGV;
    float* gtv  = sm + OFF_GTV;
    float* ct   = sm + OFF_CT;
    float* exn  = sm + OFF_EXN;
    float* part = sm + OFF_PART;

    const int b = blockIdx.x;
    const int tid = threadIdx.x;

    // --- load Wf_h^T into smem: wfT[k*128+d] = Wf[d*384+k]
    for (int i = tid; i < 128 * 128; i += 512) {
        int d = i & 127, k = i >> 7;
        wfT[i] = Wf[d * 384 + k];
    }
    // --- load h0 into smem (padded rows)
    for (int i = tid; i < NSKILL * DK; i += 512) {
        int s = i >> 7, k = i & 127;
        h[s * HPAD + k] = h0[i];
    }
    __syncthreads();

    // --- initial h_tilde = kv[:,0] . h0 ---
    {
        int e0 = eid[b * NS + 0];
        if (tid < 256) kvn[tid] = qm[e0 * NSKILL + tid];
    }
    __syncthreads();
    {
        int d = tid & 127, c = tid >> 7;
        float a = 0.f;
        const float* kp = kvn + c * 64;
        const float* hp = h + (c * 64) * HPAD + d;
        #pragma unroll 8
        for (int s = 0; s < 64; s++) a = fmaf(kp[s], hp[s * HPAD], a);
        part[c * 128 + d] = a;
    }
    __syncthreads();
    if (tid < 128)
        x4[384 + tid] = part[tid] + part[128 + tid] + part[256 + tid] + part[384 + tid];
    __syncthreads();

    for (int t = 0; t < NS - 1; t++) {
        // ---------- Phase A: gathers + build x4 ----------
        const int e_t = eid[b * NS + t];
        const int e_n = eid[b * NS + t + 1];
        const int it_n = itid[b * NS + t + 1];
        if (tid < 128) {
            float oldlv = (t == 0) ? 0.f : x4[256 + tid];   // learning_pre = prev lv
            x4[tid]        = oldlv;
            x4[128 + tid]  = it_table[it_n * 128 + tid];    // itv
            x4[256 + tid]  = g_le[(b * NS + t) * 128 + tid];// lv
            exn[tid]       = ex_table[e_n * 128 + tid];
        } else {
            int s = tid - 128;
            if (s < 256) {
                kvt[s] = qm[e_t * NSKILL + s];
                kvn[s] = qm[e_n * NSKILL + s];
            }
        }
        __syncthreads();

        // ---------- Phase B: lg / gate (x4 @ Wl^T, x4 @ Wg^T), split-K by 2 ----------
        {
            int which = tid >> 8;              // 0 -> Wl, 1 -> Wg
            int r = tid & 255;
            int d = r >> 1, half = r & 1;
            const float* Wrow = (which ? Wg : Wl) + d * 512 + half * 256;
            const float* xv = x4 + half * 256;
            float a = 0.f;
            #pragma unroll 8
            for (int k = 0; k < 256; k++) a = fmaf(Wrow[k], xv[k], a);
            part[tid] = a;
        }
        __syncthreads();
        if (tid < 256) {
            int which = tid >> 7, d = tid & 127;
            float v = part[which * 256 + d * 2] + part[which * 256 + d * 2 + 1];
            if (which == 0) lgv[d] = tanhf(v + bl[d]);
            else            gtv[d] = sigm(v + bg[d]);
        }
        __syncthreads();
        if (tid < 128) LG[tid] = gtv[tid] * (lgv[tid] + 1.0f) * 0.5f;
        __syncthreads();

        // ---------- cterm[d] = LG . Wf[d,128:256] + itv . Wf[d,256:384] ----------
        if (tid < 256) {
            int d = tid >> 1, half = tid & 1;
            const float* row = Wf + d * 384 + 128 + half * 128;
            const float* vec = half ? (x4 + 128) : LG;
            float a = 0.f;
            #pragma unroll 8
            for (int k = 0; k < 128; k++) a = fmaf(row[k], vec[k], a);
            part[tid] = a;
        }
        __syncthreads();
        if (tid < 128) ct[tid] = part[tid * 2] + part[tid * 2 + 1] + bf[tid];
        __syncthreads();

        // ---------- Phase C: f = sigmoid(h @ Wf_h^T + ct); h = kv_t*LG + f*h ----------
        {
            const int d0 = (tid & 15) * 4;      // covers d0..d0+3 and d0+64..d0+67
            const int s0 = (tid >> 4) * 8;      // 8 consecutive skills
            float acc[8][8];
            #pragma unroll
            for (int i = 0; i < 8; i++)
                #pragma unroll
                for (int j = 0; j < 8; j++) acc[i][j] = 0.f;

            #pragma unroll 1
            for (int k = 0; k < 128; k += 4) {
                #pragma unroll
                for (int kk = 0; kk < 4; kk++) {
                    float4 wa = *(const float4*)(wfT + (k + kk) * 128 + d0);
                    float4 wb = *(const float4*)(wfT + (k + kk) * 128 + d0 + 64);
                    #pragma unroll
                    for (int i = 0; i < 8; i++) {
                        float hx = h[(s0 + i) * HPAD + k + kk];
                        acc[i][0] = fmaf(hx, wa.x, acc[i][0]);
                        acc[i][1] = fmaf(hx, wa.y, acc[i][1]);
                        acc[i][2] = fmaf(hx, wa.z, acc[i][2]);
                        acc[i][3] = fmaf(hx, wa.w, acc[i][3]);
                        acc[i][4] = fmaf(hx, wb.x, acc[i][4]);
                        acc[i][5] = fmaf(hx, wb.y, acc[i][5]);
                        acc[i][6] = fmaf(hx, wb.z, acc[i][6]);
                        acc[i][7] = fmaf(hx, wb.w, acc[i][7]);
                    }
                }
            }
            __syncthreads();   // all dot-product reads of h finished

            #pragma unroll
            for (int i = 0; i < 8; i++) {
                int s = s0 + i;
                float kvts = kvt[s];
                #pragma unroll
                for (int j = 0; j < 8; j++) {
                    int d = (j < 4) ? (d0 + j) : (d0 + 60 + j);
                    float fv = sigm(acc[i][j] + ct[d]);
                    float hn = fmaf(fv, h[s * HPAD + d], kvts * LG[d]);
                    h[s * HPAD + d] = hn;     // exclusive (s,d) tile per thread
                }
            }
        }
        __syncthreads();

        // ---------- Phase D: h_tilde = kv_next . h ; pred ----------
        {
            int d = tid & 127, c = tid >> 7;
            float a = 0.f;
            const float* kp = kvn + c * 64;
            const float* hp = h + (c * 64) * HPAD + d;
            #pragma unroll 8
            for (int s = 0; s < 64; s++) a = fmaf(kp[s], hp[s * HPAD], a);
            part[c * 128 + d] = a;
        }
        __syncthreads();
        if (tid < 128)
            x4[384 + tid] = part[tid] + part[128 + tid] + part[256 + tid] + part[384 + tid];
        __syncthreads();
        if (tid < 128) {
            int d = tid;
            const float* row = Wp + d * 256;
            float a = bp[d];
            #pragma unroll 8
            for (int k = 0; k < 128; k++) {
                a = fmaf(exn[k], row[k], a);
                a = fmaf(x4[384 + k], row[128 + k], a);
            }
            out[(b * (NS - 1) + t) * 128 + d] = sigm(a);
        }
        __syncthreads();
    }
}

extern "C" void kernel_launch(void* const* d_in, const int* in_sizes, int n_in,
                              void* d_out, int out_size) {
    const int*   eid       = (const int*)d_in[0];
    const int*   atid      = (const int*)d_in[1];
    const int*   itid      = (const int*)d_in[2];
    const int*   av        = (const int*)d_in[3];
    const float* qm        = (const float*)d_in[4];
    const float* ex_table  = (const float*)d_in[5];
    const float* at_table  = (const float*)d_in[6];
    const float* it_table  = (const float*)d_in[7];
    const float* W1        = (const float*)d_in[8];
    const float* b1        = (const float*)d_in[9];
    const float* Wl        = (const float*)d_in[10];
    const float* bl        = (const float*)d_in[11];
    const float* Wg        = (const float*)d_in[12];
    const float* bg        = (const float*)d_in[13];
    const float* Wf        = (const float*)d_in[14];
    const float* bf        = (const float*)d_in[15];
    const float* Wp        = (const float*)d_in[16];
    const float* bp        = (const float*)d_in[17];
    const float* h0        = (const float*)d_in[18];
    float* out = (float*)d_out;

    size_t smem_bytes = (size_t)SMEM_FLOATS * sizeof(float);
    cudaFuncSetAttribute(lpkt_main, cudaFuncAttributeMaxDynamicSharedMemorySize,
                         (int)smem_bytes);

    answ_kernel<<<1, 128>>>(W1);
    le_kernel<<<NB * NS, 128>>>(eid, atid, av, ex_table, at_table, W1, b1);
    lpkt_main<<<NB, 512, smem_bytes>>>(eid, itid, qm, ex_table, it_table,
                                       Wl, bl, Wg, bg, Wf, bf, Wp, bp, h0, out);
}

// round 8
// speedup vs baseline: 1.0028x; 1.0005x over previous
#include <cuda_runtime.h>

#define NB 32
#define NS 128
#define NSKILL 256
#define DK 128
#define HPAD 132            // padded row length for h in smem (bank-conflict avoidance)

// ---- shared memory layout (floats) ----
#define OFF_H    0                      // 256*132 = 33792
#define OFF_WFT  33792                  // 128*128 = 16384
#define OFF_KVT  (OFF_WFT + 16384)      // 256
#define OFF_KVN  (OFF_KVT + 256)       // 256
#define OFF_X4   (OFF_KVN + 256)       // 512 : [learning | itv | lv | h_tilde]
#define OFF_LG   (OFF_X4 + 512)        // 128
#define OFF_LGV  (OFF_LG + 128)        // 128
#define OFF_GTV  (OFF_LGV + 128)       // 128
#define OFF_CT   (OFF_GTV + 128)       // 128
#define OFF_EXN  (OFF_CT + 128)        // 128
#define OFF_PART (OFF_EXN + 128)       // 512
#define SMEM_FLOATS (OFF_PART + 512)   // 52352 floats = 209408 bytes

__device__ float g_le[NB * NS * DK];   // precomputed learning embedding
__device__ float g_ansW[DK];           // rowsum of W1 answer block

__device__ __forceinline__ float sigm(float x) {
    return __fdividef(1.0f, 1.0f + __expf(-x));
}

// ---------------- precompute: ansW[d] = sum_k W1[d, 256+k] ----------------
__global__ void answ_kernel(const float* __restrict__ W1) {
    int d = threadIdx.x;
    float a = 0.f;
    #pragma unroll 8
    for (int k = 0; k < 128; k++) a += W1[d * 384 + 256 + k];
    g_ansW[d] = a;
}

// ---------------- precompute: le[b,t,:] for all (b,t) ----------------
__global__ void le_kernel(const int* __restrict__ eid, const int* __restrict__ atid,
                          const int* __restrict__ av,
                          const float* __restrict__ ex_table,
                          const float* __restrict__ at_table,
                          const float* __restrict__ W1, const float* __restrict__ b1) {
    __shared__ float exs[128], ats[128];
    int bt = blockIdx.x;          // 0 .. B*S-1
    int d = threadIdx.x;
    exs[d] = ex_table[eid[bt] * 128 + d];
    ats[d] = at_table[atid[bt] * 128 + d];
    __syncthreads();
    const float* row = W1 + d * 384;
    float acc = b1[d] + (float)av[bt] * g_ansW[d];
    #pragma unroll 8
    for (int k = 0; k < 128; k++) {
        acc = fmaf(row[k], exs[k], acc);
        acc = fmaf(row[128 + k], ats[k], acc);
    }
    g_le[bt * 128 + d] = acc;
}

// ---------------- main persistent recurrence: 1 CTA per batch ----------------
__global__ __launch_bounds__(512, 1) void lpkt_main(
    const int* __restrict__ eid, const int* __restrict__ itid,
    const float* __restrict__ qm,
    const float* __restrict__ ex_table, const float* __restrict__ it_table,
    const float* __restrict__ Wl, const float* __restrict__ bl,
    const float* __restrict__ Wg, const float* __restrict__ bg,
    const float* __restrict__ Wf, const float* __restrict__ bf,
    const float* __restrict__ Wp, const float* __restrict__ bp,
    const float* __restrict__ h0,
    float* __restrict__ out)
{
    extern __shared__ float sm[];
    float* h    = sm + OFF_H;
    float* wfT  = sm + OFF_WFT;
    float* kvt  = sm + OFF_KVT;
    float* kvn  = sm + OFF_KVN;
    float* x4   = sm + OFF_X4;
    float* LG   = sm + OFF_LG;
    float* lgv  = sm + OFF_LGV;
    float* gtv  = sm + OFF_GTV;
    float* ct   = sm + OFF_CT;
    float* exn  = sm + OFF_EXN;
    float* part = sm + OFF_PART;

    const int b = blockIdx.x;
    const int tid = threadIdx.x;

    // --- load Wf_h^T into smem: wfT[k*128+d] = Wf[d*384+k]
    for (int i = tid; i < 128 * 128; i += 512) {
        int d = i & 127, k = i >> 7;
        wfT[i] = Wf[d * 384 + k];
    }
    // --- load h0 into smem (padded rows)
    for (int i = tid; i < NSKILL * DK; i += 512) {
        int s = i >> 7, k = i & 127;
        h[s * HPAD + k] = h0[i];
    }
    __syncthreads();

    // --- initial h_tilde = kv[:,0] . h0 ---
    {
        int e0 = eid[b * NS + 0];
        if (tid < 256) kvn[tid] = qm[e0 * NSKILL + tid];
    }
    __syncthreads();
    {
        int d = tid & 127, c = tid >> 7;
        float a = 0.f;
        const float* kp = kvn + c * 64;
        const float* hp = h + (c * 64) * HPAD + d;
        #pragma unroll 8
        for (int s = 0; s < 64; s++) a = fmaf(kp[s], hp[s * HPAD], a);
        part[c * 128 + d] = a;
    }
    __syncthreads();
    if (tid < 128)
        x4[384 + tid] = part[tid] + part[128 + tid] + part[256 + tid] + part[384 + tid];
    __syncthreads();

    for (int t = 0; t < NS - 1; t++) {
        // ---------- Phase A: gathers + build x4 ----------
        const int e_t = eid[b * NS + t];
        const int e_n = eid[b * NS + t + 1];
        const int it_n = itid[b * NS + t + 1];
        if (tid < 128) {
            float oldlv = (t == 0) ? 0.f : x4[256 + tid];   // learning_pre = prev lv
            x4[tid]        = oldlv;
            x4[128 + tid]  = it_table[it_n * 128 + tid];    // itv
            x4[256 + tid]  = g_le[(b * NS + t) * 128 + tid];// lv
            exn[tid]       = ex_table[e_n * 128 + tid];
        } else {
            int s = tid - 128;
            if (s < 256) {
                kvt[s] = qm[e_t * NSKILL + s];
                kvn[s] = qm[e_n * NSKILL + s];
            }
        }
        __syncthreads();

        // ---------- Phase B: lg / gate (x4 @ Wl^T, x4 @ Wg^T), split-K by 2 ----------
        {
            int which = tid >> 8;              // 0 -> Wl, 1 -> Wg
            int r = tid & 255;
            int d = r >> 1, half = r & 1;
            const float* Wrow = (which ? Wg : Wl) + d * 512 + half * 256;
            const float* xv = x4 + half * 256;
            float a = 0.f;
            #pragma unroll 8
            for (int k = 0; k < 256; k++) a = fmaf(Wrow[k], xv[k], a);
            part[tid] = a;
        }
        __syncthreads();
        if (tid < 256) {
            int which = tid >> 7, d = tid & 127;
            float v = part[which * 256 + d * 2] + part[which * 256 + d * 2 + 1];
            if (which == 0) lgv[d] = tanhf(v + bl[d]);
            else            gtv[d] = sigm(v + bg[d]);
        }
        __syncthreads();
        if (tid < 128) LG[tid] = gtv[tid] * (lgv[tid] + 1.0f) * 0.5f;
        __syncthreads();

        // ---------- cterm[d] = LG . Wf[d,128:256] + itv . Wf[d,256:384] ----------
        if (tid < 256) {
            int d = tid >> 1, half = tid & 1;
            const float* row = Wf + d * 384 + 128 + half * 128;
            const float* vec = half ? (x4 + 128) : LG;
            float a = 0.f;
            #pragma unroll 8
            for (int k = 0; k < 128; k++) a = fmaf(row[k], vec[k], a);
            part[tid] = a;
        }
        __syncthreads();
        if (tid < 128) ct[tid] = part[tid * 2] + part[tid * 2 + 1] + bf[tid];
        __syncthreads();

        // ---------- Phase C: f = sigmoid(h @ Wf_h^T + ct); h = kv_t*LG + f*h ----------
        {
            const int d0 = (tid & 15) * 4;      // covers d0..d0+3 and d0+64..d0+67
            const int s0 = (tid >> 4) * 8;      // 8 consecutive skills
            float acc[8][8];
            #pragma unroll
            for (int i = 0; i < 8; i++)
                #pragma unroll
                for (int j = 0; j < 8; j++) acc[i][j] = 0.f;

            #pragma unroll 1
            for (int k = 0; k < 128; k += 4) {
                #pragma unroll
                for (int kk = 0; kk < 4; kk++) {
                    float4 wa = *(const float4*)(wfT + (k + kk) * 128 + d0);
                    float4 wb = *(const float4*)(wfT + (k + kk) * 128 + d0 + 64);
                    #pragma unroll
                    for (int i = 0; i < 8; i++) {
                        float hx = h[(s0 + i) * HPAD + k + kk];
                        acc[i][0] = fmaf(hx, wa.x, acc[i][0]);
                        acc[i][1] = fmaf(hx, wa.y, acc[i][1]);
                        acc[i][2] = fmaf(hx, wa.z, acc[i][2]);
                        acc[i][3] = fmaf(hx, wa.w, acc[i][3]);
                        acc[i][4] = fmaf(hx, wb.x, acc[i][4]);
                        acc[i][5] = fmaf(hx, wb.y, acc[i][5]);
                        acc[i][6] = fmaf(hx, wb.z, acc[i][6]);
                        acc[i][7] = fmaf(hx, wb.w, acc[i][7]);
                    }
                }
            }
            __syncthreads();   // all dot-product reads of h finished

            #pragma unroll
            for (int i = 0; i < 8; i++) {
                int s = s0 + i;
                float kvts = kvt[s];
                #pragma unroll
                for (int j = 0; j < 8; j++) {
                    int d = (j < 4) ? (d0 + j) : (d0 + 60 + j);
                    float fv = sigm(acc[i][j] + ct[d]);
                    float hn = fmaf(fv, h[s * HPAD + d], kvts * LG[d]);
                    h[s * HPAD + d] = hn;     // exclusive (s,d) tile per thread
                }
            }
        }
        __syncthreads();

        // ---------- Phase D: h_tilde = kv_next . h ; pred ----------
        {
            int d = tid & 127, c = tid >> 7;
            float a = 0.f;
            const float* kp = kvn + c * 64;
            const float* hp = h + (c * 64) * HPAD + d;
            #pragma unroll 8
            for (int s = 0; s < 64; s++) a = fmaf(kp[s], hp[s * HPAD], a);
            part[c * 128 + d] = a;
        }
        __syncthreads();
        if (tid < 128)
            x4[384 + tid] = part[tid] + part[128 + tid] + part[256 + tid] + part[384 + tid];
        __syncthreads();
        if (tid < 128) {
            int d = tid;
            const float* row = Wp + d * 256;
            float a = bp[d];
            #pragma unroll 8
            for (int k = 0; k < 128; k++) {
                a = fmaf(exn[k], row[k], a);
                a = fmaf(x4[384 + k], row[128 + k], a);
            }
            out[(b * (NS - 1) + t) * 128 + d] = sigm(a);
        }
        __syncthreads();
    }
}

extern "C" void kernel_launch(void* const* d_in, const int* in_sizes, int n_in,
                              void* d_out, int out_size) {
    const int*   eid       = (const int*)d_in[0];
    const int*   atid      = (const int*)d_in[1];
    const int*   itid      = (const int*)d_in[2];
    const int*   av        = (const int*)d_in[3];
    const float* qm        = (const float*)d_in[4];
    const float* ex_table  = (const float*)d_in[5];
    const float* at_table  = (const float*)d_in[6];
    const float* it_table  = (const float*)d_in[7];
    const float* W1        = (const float*)d_in[8];
    const float* b1        = (const float*)d_in[9];
    const float* Wl        = (const float*)d_in[10];
    const float* bl        = (const float*)d_in[11];
    const float* Wg        = (const float*)d_in[12];
    const float* bg        = (const float*)d_in[13];
    const float* Wf        = (const float*)d_in[14];
    const float* bf        = (const float*)d_in[15];
    const float* Wp        = (const float*)d_in[16];
    const float* bp        = (const float*)d_in[17];
    const float* h0        = (const float*)d_in[18];
    float* out = (float*)d_out;

    size_t smem_bytes = (size_t)SMEM_FLOATS * sizeof(float);
    cudaFuncSetAttribute(lpkt_main, cudaFuncAttributeMaxDynamicSharedMemorySize,
                         (int)smem_bytes);

    answ_kernel<<<1, 128>>>(W1);
    le_kernel<<<NB * NS, 128>>>(eid, atid, av, ex_table, at_table, W1, b1);
    lpkt_main<<<NB, 512, smem_bytes>>>(eid, itid, qm, ex_table, it_table,
                                       Wl, bl, Wg, bg, Wf, bf, Wp, bp, h0, out);
}

// round 9
// speedup vs baseline: 1.0030x; 1.0001x over previous
#include <cuda_runtime.h>

#define NB 32
#define NS 128
#define NSKILL 256
#define DK 128
#define HPAD 132            // padded row length for h in smem (bank-conflict avoidance)

// ---- shared memory layout (floats) ----
#define OFF_H    0                      // 256*132 = 33792
#define OFF_WFT  33792                  // 128*128 = 16384
#define OFF_KVT  (OFF_WFT + 16384)      // 256
#define OFF_KVN  (OFF_KVT + 256)       // 256
#define OFF_X4   (OFF_KVN + 256)       // 512 : [learning | itv | lv | h_tilde]
#define OFF_LG   (OFF_X4 + 512)        // 128
#define OFF_LGV  (OFF_LG + 128)        // 128
#define OFF_GTV  (OFF_LGV + 128)       // 128
#define OFF_CT   (OFF_GTV + 128)       // 128
#define OFF_EXN  (OFF_CT + 128)        // 128
#define OFF_PART (OFF_EXN + 128)       // 512
#define SMEM_FLOATS (OFF_PART + 512)   // 52352 floats = 209408 bytes

__device__ float g_le[NB * NS * DK];   // precomputed learning embedding
__device__ float g_ansW[DK];           // rowsum of W1 answer block

__device__ __forceinline__ float sigm(float x) {
    return __fdividef(1.0f, 1.0f + __expf(-x));
}

// ---------------- precompute: ansW[d] = sum_k W1[d, 256+k] ----------------
__global__ void answ_kernel(const float* __restrict__ W1) {
    int d = threadIdx.x;
    float a = 0.f;
    #pragma unroll 8
    for (int k = 0; k < 128; k++) a += W1[d * 384 + 256 + k];
    g_ansW[d] = a;
}

// ---------------- precompute: le[b,t,:] for all (b,t) ----------------
__global__ void le_kernel(const int* __restrict__ eid, const int* __restrict__ atid,
                          const int* __restrict__ av,
                          const float* __restrict__ ex_table,
                          const float* __restrict__ at_table,
                          const float* __restrict__ W1, const float* __restrict__ b1) {
    __shared__ float exs[128], ats[128];
    int bt = blockIdx.x;          // 0 .. B*S-1
    int d = threadIdx.x;
    exs[d] = ex_table[eid[bt] * 128 + d];
    ats[d] = at_table[atid[bt] * 128 + d];
    __syncthreads();
    const float* row = W1 + d * 384;
    float acc = b1[d] + (float)av[bt] * g_ansW[d];
    #pragma unroll 8
    for (int k = 0; k < 128; k++) {
        acc = fmaf(row[k], exs[k], acc);
        acc = fmaf(row[128 + k], ats[k], acc);
    }
    g_le[bt * 128 + d] = acc;
}

// ---------------- main persistent recurrence: 1 CTA per batch ----------------
__global__ __launch_bounds__(512, 1) void lpkt_main(
    const int* __restrict__ eid, const int* __restrict__ itid,
    const float* __restrict__ qm,
    const float* __restrict__ ex_table, const float* __restrict__ it_table,
    const float* __restrict__ Wl, const float* __restrict__ bl,
    const float* __restrict__ Wg, const float* __restrict__ bg,
    const float* __restrict__ Wf, const float* __restrict__ bf,
    const float* __restrict__ Wp, const float* __restrict__ bp,
    const float* __restrict__ h0,
    float* __restrict__ out)
{
    extern __shared__ float sm[];
    float* h    = sm + OFF_H;
    float* wfT  = sm + OFF_WFT;
    float* kvt  = sm + OFF_KVT;
    float* kvn  = sm + OFF_KVN;
    float* x4   = sm + OFF_X4;
    float* LG   = sm + OFF_LG;
    float* lgv  = sm + OFF_LGV;
    float* gtv  = sm + OFF_GTV;
    float* ct   = sm + OFF_CT;
    float* exn  = sm + OFF_EXN;
    float* part = sm + OFF_PART;

    const int b = blockIdx.x;
    const int tid = threadIdx.x;

    // --- load Wf_h^T into smem: wfT[k*128+d] = Wf[d*384+k]
    for (int i = tid; i < 128 * 128; i += 512) {
        int d = i & 127, k = i >> 7;
        wfT[i] = Wf[d * 384 + k];
    }
    // --- load h0 into smem (padded rows)
    for (int i = tid; i < NSKILL * DK; i += 512) {
        int s = i >> 7, k = i & 127;
        h[s * HPAD + k] = h0[i];
    }
    __syncthreads();

    // --- initial h_tilde = kv[:,0] . h0 ---
    {
        int e0 = eid[b * NS + 0];
        if (tid < 256) kvn[tid] = qm[e0 * NSKILL + tid];
    }
    __syncthreads();
    {
        int d = tid & 127, c = tid >> 7;
        float a = 0.f;
        const float* kp = kvn + c * 64;
        const float* hp = h + (c * 64) * HPAD + d;
        #pragma unroll 8
        for (int s = 0; s < 64; s++) a = fmaf(kp[s], hp[s * HPAD], a);
        part[c * 128 + d] = a;
    }
    __syncthreads();
    if (tid < 128)
        x4[384 + tid] = part[tid] + part[128 + tid] + part[256 + tid] + part[384 + tid];
    __syncthreads();

    for (int t = 0; t < NS - 1; t++) {
        // ---------- Phase A: gathers + build x4 ----------
        const int e_t = eid[b * NS + t];
        const int e_n = eid[b * NS + t + 1];
        const int it_n = itid[b * NS + t + 1];
        if (tid < 128) {
            float oldlv = (t == 0) ? 0.f : x4[256 + tid];   // learning_pre = prev lv
            x4[tid]        = oldlv;
            x4[128 + tid]  = it_table[it_n * 128 + tid];    // itv
            x4[256 + tid]  = g_le[(b * NS + t) * 128 + tid];// lv
            exn[tid]       = ex_table[e_n * 128 + tid];
        } else {
            int s = tid - 128;
            if (s < 256) {
                kvt[s] = qm[e_t * NSKILL + s];
                kvn[s] = qm[e_n * NSKILL + s];
            }
        }
        __syncthreads();

        // ---------- Phase B: lg / gate (x4 @ Wl^T, x4 @ Wg^T), split-K by 2 ----------
        {
            int which = tid >> 8;              // 0 -> Wl, 1 -> Wg
            int r = tid & 255;
            int d = r >> 1, half = r & 1;
            const float* Wrow = (which ? Wg : Wl) + d * 512 + half * 256;
            const float* xv = x4 + half * 256;
            float a = 0.f;
            #pragma unroll 8
            for (int k = 0; k < 256; k++) a = fmaf(Wrow[k], xv[k], a);
            part[tid] = a;
        }
        __syncthreads();
        if (tid < 256) {
            int which = tid >> 7, d = tid & 127;
            float v = part[which * 256 + d * 2] + part[which * 256 + d * 2 + 1];
            if (which == 0) lgv[d] = tanhf(v + bl[d]);
            else            gtv[d] = sigm(v + bg[d]);
        }
        __syncthreads();
        if (tid < 128) LG[tid] = gtv[tid] * (lgv[tid] + 1.0f) * 0.5f;
        __syncthreads();

        // ---------- cterm[d] = LG . Wf[d,128:256] + itv . Wf[d,256:384] ----------
        if (tid < 256) {
            int d = tid >> 1, half = tid & 1;
            const float* row = Wf + d * 384 + 128 + half * 128;
            const float* vec = half ? (x4 + 128) : LG;
            float a = 0.f;
            #pragma unroll 8
            for (int k = 0; k < 128; k++) a = fmaf(row[k], vec[k], a);
            part[tid] = a;
        }
        __syncthreads();
        if (tid < 128) ct[tid] = part[tid * 2] + part[tid * 2 + 1] + bf[tid];
        __syncthreads();

        // ---------- Phase C: f = sigmoid(h @ Wf_h^T + ct); h = kv_t*LG + f*h ----------
        {
            const int d0 = (tid & 15) * 4;      // covers d0..d0+3 and d0+64..d0+67
            const int s0 = (tid >> 4) * 8;      // 8 consecutive skills
            float acc[8][8];
            #pragma unroll
            for (int i = 0; i < 8; i++)
                #pragma unroll
                for (int j = 0; j < 8; j++) acc[i][j] = 0.f;

            #pragma unroll 1
            for (int k = 0; k < 128; k += 4) {
                #pragma unroll
                for (int kk = 0; kk < 4; kk++) {
                    float4 wa = *(const float4*)(wfT + (k + kk) * 128 + d0);
                    float4 wb = *(const float4*)(wfT + (k + kk) * 128 + d0 + 64);
                    #pragma unroll
                    for (int i = 0; i < 8; i++) {
                        float hx = h[(s0 + i) * HPAD + k + kk];
                        acc[i][0] = fmaf(hx, wa.x, acc[i][0]);
                        acc[i][1] = fmaf(hx, wa.y, acc[i][1]);
                        acc[i][2] = fmaf(hx, wa.z, acc[i][2]);
                        acc[i][3] = fmaf(hx, wa.w, acc[i][3]);
                        acc[i][4] = fmaf(hx, wb.x, acc[i][4]);
                        acc[i][5] = fmaf(hx, wb.y, acc[i][5]);
                        acc[i][6] = fmaf(hx, wb.z, acc[i][6]);
                        acc[i][7] = fmaf(hx, wb.w, acc[i][7]);
                    }
                }
            }
            __syncthreads();   // all dot-product reads of h finished

            #pragma unroll
            for (int i = 0; i < 8; i++) {
                int s = s0 + i;
                float kvts = kvt[s];
                #pragma unroll
                for (int j = 0; j < 8; j++) {
                    int d = (j < 4) ? (d0 + j) : (d0 + 60 + j);
                    float fv = sigm(acc[i][j] + ct[d]);
                    float hn = fmaf(fv, h[s * HPAD + d], kvts * LG[d]);
                    h[s * HPAD + d] = hn;     // exclusive (s,d) tile per thread
                }
            }
        }
        __syncthreads();

        // ---------- Phase D: h_tilde = kv_next . h ; pred ----------
        {
            int d = tid & 127, c = tid >> 7;
            float a = 0.f;
            const float* kp = kvn + c * 64;
            const float* hp = h + (c * 64) * HPAD + d;
            #pragma unroll 8
            for (int s = 0; s < 64; s++) a = fmaf(kp[s], hp[s * HPAD], a);
            part[c * 128 + d] = a;
        }
        __syncthreads();
        if (tid < 128)
            x4[384 + tid] = part[tid] + part[128 + tid] + part[256 + tid] + part[384 + tid];
        __syncthreads();
        if (tid < 128) {
            int d = tid;
            const float* row = Wp + d * 256;
            float a = bp[d];
            #pragma unroll 8
            for (int k = 0; k < 128; k++) {
                a = fmaf(exn[k], row[k], a);
                a = fmaf(x4[384 + k], row[128 + k], a);
            }
            out[(b * (NS - 1) + t) * 128 + d] = sigm(a);
        }
        __syncthreads();
    }
}

extern "C" void kernel_launch(void* const* d_in, const int* in_sizes, int n_in,
                              void* d_out, int out_size) {
    const int*   eid       = (const int*)d_in[0];
    const int*   atid      = (const int*)d_in[1];
    const int*   itid      = (const int*)d_in[2];
    const int*   av        = (const int*)d_in[3];
    const float* qm        = (const float*)d_in[4];
    const float* ex_table  = (const float*)d_in[5];
    const float* at_table  = (const float*)d_in[6];
    const float* it_table  = (const float*)d_in[7];
    const float* W1        = (const float*)d_in[8];
    const float* b1        = (const float*)d_in[9];
    const float* Wl        = (const float*)d_in[10];
    const float* bl        = (const float*)d_in[11];
    const float* Wg        = (const float*)d_in[12];
    const float* bg        = (const float*)d_in[13];
    const float* Wf        = (const float*)d_in[14];
    const float* bf        = (const float*)d_in[15];
    const float* Wp        = (const float*)d_in[16];
    const float* bp        = (const float*)d_in[17];
    const float* h0        = (const float*)d_in[18];
    float* out = (float*)d_out;

    size_t smem_bytes = (size_t)SMEM_FLOATS * sizeof(float);
    cudaFuncSetAttribute(lpkt_main, cudaFuncAttributeMaxDynamicSharedMemorySize,
                         (int)smem_bytes);

    answ_kernel<<<1, 128>>>(W1);
    le_kernel<<<NB * NS, 128>>>(eid, atid, av, ex_table, at_table, W1, b1);
    lpkt_main<<<NB, 512, smem_bytes>>>(eid, itid, qm, ex_table, it_table,
                                       Wl, bl, Wg, bg, Wf, bf, Wp, bp, h0, out);
}